// round 8
// baseline (speedup 1.0000x reference)
#include <cuda_runtime.h>

#define NN   8
#define CIN  4
#define COUT 64
#define DIM  512
#define RANK 4
#define BT   32      // spatial tile (BT x BT)
#define NTHREADS 512

// scratch: row sums and col sums, [n][o][pos]
__device__ float g_rs[NN * COUT * DIM];
__device__ float g_cs[NN * COUT * DIM];

// ---------------------------------------------------------------------------
__global__ void k_zero() {
    int i = blockIdx.x * blockDim.x + threadIdx.x;
    if (i < NN * COUT * DIM) {
        g_rs[i] = 0.0f;
        g_cs[i] = 0.0f;
    }
}

// ---------------------------------------------------------------------------
// Pass 1: per (h-tile, w-tile), loop o (64) and n (8); compute P tile and
// reduce rows -> g_rs (warp shuffle + atomic), cols -> g_cs (smem + atomic).
// X tile held in smem, c-packed as float4 so P is one LDS.128 + dot4.
__global__ void __launch_bounds__(NTHREADS)
k_pass1(const float* __restrict__ X, const float* __restrict__ wL) {
    extern __shared__ float smem[];
    float* Xs    = smem;                          // [n][h][w] * 4c  (32768 floats)
    float* Lh    = Xs + NN * BT * BT * 4;         // [c][i][r]       (512 floats)
    float* Lw    = Lh + CIN * BT * RANK;          // [c][i][r]       (512 floats)
    float* cs_sm = Lw + CIN * BT * RANK;          // [warp16][n8][w32] (4096 floats)

    const int tid = threadIdx.x;
    const int gh0 = blockIdx.y * BT;
    const int gw0 = blockIdx.x * BT;

    // Load X tile (c-packed): Xs[((n*1024)+h*32+w)*4 + c]
    for (int idx = tid; idx < NN * CIN * BT * BT; idx += NTHREADS) {
        int w = idx & 31;
        int h = (idx >> 5) & 31;
        int c = (idx >> 10) & 3;
        int n = idx >> 12;
        float v = X[((n * CIN + c) * DIM + gh0 + h) * (long)DIM + gw0 + w];
        Xs[((n * BT * BT) + h * BT + w) * 4 + c] = v;
    }

    const int lane = tid & 31;
    const int W = tid >> 5;      // warp id 0..15 ; this thread owns rows W and W+16
    const int w = lane;

    for (int o = 0; o < COUT; o++) {
        // Load L rows for this tile (contiguous per c: 128 consecutive floats)
        {
            int c = tid >> 7;
            int i = (tid >> 2) & 31;
            int r = tid & 3;
            Lh[tid] = wL[((o * CIN + c) * DIM + gh0 + i) * RANK + r];
            Lw[tid] = wL[((o * CIN + c) * DIM + gw0 + i) * RANK + r];
        }
        __syncthreads();

        // t_c(h,w) = dot4(Lh[c][h], Lw[c][w]) for rows h=W and h=W+16
        float t0[4], t1[4];
#pragma unroll
        for (int c = 0; c < 4; c++) {
            const float* lwc = &Lw[(c * BT + w) * 4];
            const float* lh0 = &Lh[(c * BT + W) * 4];
            const float* lh1 = &Lh[(c * BT + W + 16) * 4];
            float a0 = 0.f, a1 = 0.f;
#pragma unroll
            for (int r = 0; r < 4; r++) {
                float lw_r = lwc[r];
                a0 += lh0[r] * lw_r;
                a1 += lh1[r] * lw_r;
            }
            t0[c] = a0; t1[c] = a1;
        }

        float colp[NN];
#pragma unroll
        for (int n = 0; n < NN; n++) {
            const float4 x0 = *(const float4*)&Xs[((n * BT * BT) + W * BT + w) * 4];
            const float4 x1 = *(const float4*)&Xs[((n * BT * BT) + (W + 16) * BT + w) * 4];
            float p0 = x0.x * t0[0] + x0.y * t0[1] + x0.z * t0[2] + x0.w * t0[3];
            float p1 = x1.x * t1[0] + x1.y * t1[1] + x1.z * t1[2] + x1.w * t1[3];
            colp[n] = p0 + p1;

            // row sums: reduce over w within the warp
            float r0 = p0, r1 = p1;
#pragma unroll
            for (int s = 16; s > 0; s >>= 1) {
                r0 += __shfl_xor_sync(0xffffffffu, r0, s);
                r1 += __shfl_xor_sync(0xffffffffu, r1, s);
            }
            if (lane == 0) {
                atomicAdd(&g_rs[(n * COUT + o) * DIM + gh0 + W],      r0);
                atomicAdd(&g_rs[(n * COUT + o) * DIM + gh0 + W + 16], r1);
            }
        }

        // col sums: stage per-warp partials, reduce across 16 warps
#pragma unroll
        for (int n = 0; n < NN; n++)
            cs_sm[(W * NN + n) * BT + w] = colp[n];
        __syncthreads();

        if (tid < NN * BT) {
            int n = tid >> 5;
            int ww = tid & 31;
            float s = 0.f;
#pragma unroll
            for (int Wp = 0; Wp < 16; Wp++)
                s += cs_sm[(Wp * NN + n) * BT + ww];
            atomicAdd(&g_cs[(n * COUT + o) * DIM + gw0 + ww], s);
        }
        __syncthreads();
    }
}

// ---------------------------------------------------------------------------
// Pass 2: recompute P per tile, write out = rs + cs - P + bias, zero diagonal.
// Thread mapping: h = tid>>4 (0..31), two adjacent w's -> float2 stores.
__global__ void __launch_bounds__(NTHREADS)
k_pass2(const float* __restrict__ X, const float* __restrict__ wL,
        const float* __restrict__ bias, float* __restrict__ out) {
    extern __shared__ float smem[];
    float* Xs = smem;                      // 32768 floats
    float* Lh = Xs + NN * BT * BT * 4;     // 512
    float* Lw = Lh + CIN * BT * RANK;      // 512

    const int tid = threadIdx.x;
    const int gh0 = blockIdx.y * BT;
    const int gw0 = blockIdx.x * BT;

    for (int idx = tid; idx < NN * CIN * BT * BT; idx += NTHREADS) {
        int w = idx & 31;
        int h = (idx >> 5) & 31;
        int c = (idx >> 10) & 3;
        int n = idx >> 12;
        float v = X[((n * CIN + c) * DIM + gh0 + h) * (long)DIM + gw0 + w];
        Xs[((n * BT * BT) + h * BT + w) * 4 + c] = v;
    }

    const int h  = tid >> 4;          // 0..31
    const int w0 = (tid & 15) * 2;    // 0,2,...,30
    const int hg = gh0 + h;

    for (int o = 0; o < COUT; o++) {
        {
            int c = tid >> 7;
            int i = (tid >> 2) & 31;
            int r = tid & 3;
            Lh[tid] = wL[((o * CIN + c) * DIM + gh0 + i) * RANK + r];
            Lw[tid] = wL[((o * CIN + c) * DIM + gw0 + i) * RANK + r];
        }
        __syncthreads();

        float tA[4], tB[4];
#pragma unroll
        for (int c = 0; c < 4; c++) {
            const float* lh  = &Lh[(c * BT + h) * 4];
            const float* lwA = &Lw[(c * BT + w0) * 4];
            const float* lwB = &Lw[(c * BT + w0 + 1) * 4];
            float a = 0.f, b = 0.f;
#pragma unroll
            for (int r = 0; r < 4; r++) {
                float lh_r = lh[r];
                a += lh_r * lwA[r];
                b += lh_r * lwB[r];
            }
            tA[c] = a; tB[c] = b;
        }

        const float bo = __ldg(&bias[o]);

#pragma unroll
        for (int n = 0; n < NN; n++) {
            const float4 xA = *(const float4*)&Xs[((n * BT * BT) + h * BT + w0) * 4];
            const float4 xB = *(const float4*)&Xs[((n * BT * BT) + h * BT + w0 + 1) * 4];
            float pA = xA.x * tA[0] + xA.y * tA[1] + xA.z * tA[2] + xA.w * tA[3];
            float pB = xB.x * tB[0] + xB.y * tB[1] + xB.z * tB[2] + xB.w * tB[3];

            const int base = (n * COUT + o) * DIM;
            float rsv = __ldg(&g_rs[base + hg]);
            float2 csv = *(const float2*)&g_cs[base + gw0 + w0];

            float oA = rsv + csv.x - pA + bo;
            float oB = rsv + csv.y - pB + bo;
            if (hg == gw0 + w0)     oA = 0.0f;
            if (hg == gw0 + w0 + 1) oB = 0.0f;

            float2 res = make_float2(oA, oB);
            *(float2*)&out[((long)(n * COUT + o) * DIM + hg) * DIM + gw0 + w0] = res;
        }
        __syncthreads();
    }
}

// ---------------------------------------------------------------------------
extern "C" void kernel_launch(void* const* d_in, const int* in_sizes, int n_in,
                              void* d_out, int out_size) {
    const float* X    = (const float*)d_in[0];   // (8,4,512,512) f32
    const float* wL   = (const float*)d_in[1];   // (64,4,512,4)  f32
    const float* bias = (const float*)d_in[2];   // (64,)         f32
    float* out = (float*)d_out;                  // (8,64,512,512) f32

    const int smem1 = (NN * BT * BT * 4 + 2 * CIN * BT * RANK + 16 * NN * BT) * (int)sizeof(float);
    const int smem2 = (NN * BT * BT * 4 + 2 * CIN * BT * RANK) * (int)sizeof(float);

    cudaFuncSetAttribute(k_pass1, cudaFuncAttributeMaxDynamicSharedMemorySize, smem1);
    cudaFuncSetAttribute(k_pass2, cudaFuncAttributeMaxDynamicSharedMemorySize, smem2);

    // zero rs/cs scratch (required every replay)
    k_zero<<<(NN * COUT * DIM + NTHREADS - 1) / NTHREADS, NTHREADS>>>();

    dim3 grid(DIM / BT, DIM / BT);   // (16, 16)
    k_pass1<<<grid, NTHREADS, smem1>>>(X, wL);
    k_pass2<<<grid, NTHREADS, smem2>>>(X, wL, bias, out);
}

// round 10
// speedup vs baseline: 1.7534x; 1.7534x over previous
#include <cuda_runtime.h>

#define NN   8
#define CIN  4
#define COUT 64
#define DIM  512
#define RANK 4
#define BT   32
#define NTHREADS 512

// scratch: row sums and col sums, [n][o][pos]
__device__ float g_rs[NN * COUT * DIM];
__device__ float g_cs[NN * COUT * DIM];

// ---------------------------------------------------------------------------
__global__ void k_zero() {
    int i = blockIdx.x * blockDim.x + threadIdx.x;
    if (i < NN * COUT * DIM) {
        g_rs[i] = 0.0f;
        g_cs[i] = 0.0f;
    }
}

// ---------------------------------------------------------------------------
// Pass 1: X held in registers (64 floats/thread). lane = w, warp owns rows
// W and W+16. Per o: build L in smem, compute P, reduce rows via shuffle,
// cols via smem staging; flush with spread global atomics.
__global__ void __launch_bounds__(NTHREADS)
k_pass1(const float* __restrict__ X, const float* __restrict__ wL) {
    __shared__ float Lh[CIN * BT * RANK];       // 512
    __shared__ float Lw[CIN * BT * RANK];       // 512
    __shared__ float cs_sm[16 * NN * BT];       // 4096

    const int tid  = threadIdx.x;
    const int gh0  = blockIdx.y * BT;
    const int gw0  = blockIdx.x * BT;
    const int lane = tid & 31;
    const int W    = tid >> 5;                  // warp 0..15, owns rows W, W+16

    // X into registers: xr0 = row W, xr1 = row W+16 (coalesced 128B per warp)
    float xr0[NN][CIN], xr1[NN][CIN];
#pragma unroll
    for (int n = 0; n < NN; n++)
#pragma unroll
        for (int c = 0; c < CIN; c++) {
            const float* p = X + ((long)(n * CIN + c) * DIM + gh0) * DIM + gw0 + lane;
            xr0[n][c] = p[(long)W * DIM];
            xr1[n][c] = p[(long)(W + 16) * DIM];
        }

    for (int o = 0; o < COUT; o++) {
        {
            int c = tid >> 7;
            int i = (tid >> 2) & 31;
            int r = tid & 3;
            Lh[tid] = wL[((o * CIN + c) * DIM + gh0 + i) * RANK + r];
            Lw[tid] = wL[((o * CIN + c) * DIM + gw0 + i) * RANK + r];
        }
        __syncthreads();

        float t0[CIN], t1[CIN];
#pragma unroll
        for (int c = 0; c < CIN; c++) {
            float4 lw  = *(const float4*)&Lw[(c * BT + lane) * 4];
            float4 lh0 = *(const float4*)&Lh[(c * BT + W) * 4];        // broadcast
            float4 lh1 = *(const float4*)&Lh[(c * BT + W + 16) * 4];   // broadcast
            t0[c] = lh0.x * lw.x + lh0.y * lw.y + lh0.z * lw.z + lh0.w * lw.w;
            t1[c] = lh1.x * lw.x + lh1.y * lw.y + lh1.z * lw.z + lh1.w * lw.w;
        }

#pragma unroll
        for (int n = 0; n < NN; n++) {
            float p0 = xr0[n][0] * t0[0] + xr0[n][1] * t0[1]
                     + xr0[n][2] * t0[2] + xr0[n][3] * t0[3];
            float p1 = xr1[n][0] * t1[0] + xr1[n][1] * t1[1]
                     + xr1[n][2] * t1[2] + xr1[n][3] * t1[3];

            cs_sm[(W * NN + n) * BT + lane] = p0 + p1;

            float r0 = p0, r1 = p1;
#pragma unroll
            for (int s = 16; s > 0; s >>= 1) {
                r0 += __shfl_xor_sync(0xffffffffu, r0, s);
                r1 += __shfl_xor_sync(0xffffffffu, r1, s);
            }
            if (lane == 0) {
                atomicAdd(&g_rs[(n * COUT + o) * DIM + gh0 + W],      r0);
                atomicAdd(&g_rs[(n * COUT + o) * DIM + gh0 + W + 16], r1);
            }
        }
        __syncthreads();

        if (tid < NN * BT) {
            int n  = tid >> 5;
            int ww = tid & 31;
            float s = 0.f;
#pragma unroll
            for (int Wp = 0; Wp < 16; Wp++)
                s += cs_sm[(Wp * NN + n) * BT + ww];
            atomicAdd(&g_cs[(n * COUT + o) * DIM + gw0 + ww], s);
        }
        __syncthreads();
    }
}

// ---------------------------------------------------------------------------
// Pass 2: X in registers; rs/cs tile staged in smem per o; float2 stores.
// Thread: h = tid>>4 (0..31), w0 = 2*(tid&15).
__global__ void __launch_bounds__(NTHREADS)
k_pass2(const float* __restrict__ X, const float* __restrict__ wL,
        const float* __restrict__ bias, float* __restrict__ out) {
    __shared__ float Lh[CIN * BT * RANK];    // 512
    __shared__ float Lw[CIN * BT * RANK];    // 512
    __shared__ float rs_sm[NN * BT];         // 256: [n][h]
    __shared__ float cs_sm[NN * BT];         // 256: [n][w]

    const int tid = threadIdx.x;
    const int gh0 = blockIdx.y * BT;
    const int gw0 = blockIdx.x * BT;
    const int h   = tid >> 4;
    const int w0  = (tid & 15) * 2;
    const int hg  = gh0 + h;

    // X into registers: 2 adjacent w per thread, float2 loads (coalesced)
    float xa[NN][CIN], xb[NN][CIN];
#pragma unroll
    for (int n = 0; n < NN; n++)
#pragma unroll
        for (int c = 0; c < CIN; c++) {
            float2 v = *(const float2*)&X[((long)(n * CIN + c) * DIM + hg) * DIM + gw0 + w0];
            xa[n][c] = v.x;
            xb[n][c] = v.y;
        }

    for (int o = 0; o < COUT; o++) {
        {
            int c = tid >> 7;
            int i = (tid >> 2) & 31;
            int r = tid & 3;
            Lh[tid] = wL[((o * CIN + c) * DIM + gh0 + i) * RANK + r];
            Lw[tid] = wL[((o * CIN + c) * DIM + gw0 + i) * RANK + r];
        }
        // stage rs/cs tile for this o: 512 floats, 1 per thread, coalesced
        {
            int n = tid >> 6;          // 0..7
            int i = tid & 63;          // 0..63 : first 32 -> rs, next 32 -> cs
            int base = (n * COUT + o) * DIM;
            if (i < 32) rs_sm[n * BT + i]        = g_rs[base + gh0 + i];
            else        cs_sm[n * BT + (i - 32)] = g_cs[base + gw0 + (i - 32)];
        }
        __syncthreads();

        float tA[CIN], tB[CIN];
#pragma unroll
        for (int c = 0; c < CIN; c++) {
            float4 lh  = *(const float4*)&Lh[(c * BT + h) * 4];          // broadcast
            float4 lwA = *(const float4*)&Lw[(c * BT + w0) * 4];
            float4 lwB = *(const float4*)&Lw[(c * BT + w0 + 1) * 4];
            tA[c] = lh.x * lwA.x + lh.y * lwA.y + lh.z * lwA.z + lh.w * lwA.w;
            tB[c] = lh.x * lwB.x + lh.y * lwB.y + lh.z * lwB.z + lh.w * lwB.w;
        }

        const float bo = __ldg(&bias[o]);

#pragma unroll
        for (int n = 0; n < NN; n++) {
            float pA = xa[n][0] * tA[0] + xa[n][1] * tA[1]
                     + xa[n][2] * tA[2] + xa[n][3] * tA[3];
            float pB = xb[n][0] * tB[0] + xb[n][1] * tB[1]
                     + xb[n][2] * tB[2] + xb[n][3] * tB[3];

            float rsv = rs_sm[n * BT + h];
            float csA = cs_sm[n * BT + w0];
            float csB = cs_sm[n * BT + w0 + 1];

            float oA = rsv + csA - pA + bo;
            float oB = rsv + csB - pB + bo;
            if (hg == gw0 + w0)     oA = 0.0f;
            if (hg == gw0 + w0 + 1) oB = 0.0f;

            *(float2*)&out[((long)(n * COUT + o) * DIM + hg) * DIM + gw0 + w0]
                = make_float2(oA, oB);
        }
        __syncthreads();
    }
}

// ---------------------------------------------------------------------------
extern "C" void kernel_launch(void* const* d_in, const int* in_sizes, int n_in,
                              void* d_out, int out_size) {
    const float* X    = (const float*)d_in[0];   // (8,4,512,512) f32
    const float* wL   = (const float*)d_in[1];   // (64,4,512,4)  f32
    const float* bias = (const float*)d_in[2];   // (64,)         f32
    float* out = (float*)d_out;                  // (8,64,512,512) f32

    k_zero<<<(NN * COUT * DIM + NTHREADS - 1) / NTHREADS, NTHREADS>>>();

    dim3 grid(DIM / BT, DIM / BT);   // (16, 16)
    k_pass1<<<grid, NTHREADS>>>(X, wL);
    k_pass2<<<grid, NTHREADS>>>(X, wL, bias, out);
}